// round 4
// baseline (speedup 1.0000x reference)
#include <cuda_runtime.h>

// Problem shape (fixed by reference setup_inputs)
#define BB 128
#define AA 1024
#define MM 6
#define TT 16
#define THREADS 1024                        // 1 agent per thread
#define NWARPS (THREADS / 32)               // 32

#define AGENT_THRESH 0.5f
#define X_DIS_THRESH 1.5f
#define Y_DIS_THRESH 3.0f
#define DIS_THRESH_SQ 9.0f                  // dist > 3  <=>  dx*dx+dy*dy > 9
#define MEAN_SCALE (1.0f / (float)(BB * TT * 2))   // mean over [B,T,2]

__global__ void zero_out_kernel(float* out) { out[0] = 0.0f; }

__global__ __launch_bounds__(THREADS, 1)
void plan_pred_collision_loss_kernel(
    const float* __restrict__ ego_plan,   // [B, T, 2]
    const float* __restrict__ preds,      // [B, A, M, T, 2]
    const float* __restrict__ scores,     // [B, A, M]
    const float* __restrict__ pmask,      // [B, T]
    float* __restrict__ out)              // scalar
{
    const int b    = blockIdx.x;
    const int tid  = threadIdx.x;
    const int wid  = tid >> 5;
    const int lane = tid & 31;
    const int a    = tid;                 // one agent per thread

    __shared__ float s_ego[TT * 2];
    __shared__ float s_pmask[TT];
    __shared__ float s_xw[NWARPS][TT];
    __shared__ float s_yw[NWARPS][TT];

    if (tid < TT * 2) s_ego[tid] = ego_plan[b * TT * 2 + tid];
    if (tid < TT)     s_pmask[tid] = pmask[b * TT + tid];
    __syncthreads();

    // ---- argmax over modes (first-max wins, like jnp.argmax) ----
    const float* sc = scores + ((size_t)b * AA + a) * MM;
    float s0 = __ldg(&sc[0]);
    float s1 = __ldg(&sc[1]);
    float s2 = __ldg(&sc[2]);
    float s3 = __ldg(&sc[3]);
    float s4 = __ldg(&sc[4]);
    float s5 = __ldg(&sc[5]);
    float best = s0; int bm = 0;
    if (s1 > best) { best = s1; bm = 1; }
    if (s2 > best) { best = s2; bm = 2; }
    if (s3 > best) { best = s3; bm = 3; }
    if (s4 > best) { best = s4; bm = 4; }
    if (s5 > best) { best = s5; bm = 5; }
    const float conf_pen = (best < AGENT_THRESH) ? 100.0f : 0.0f;

    // ---- gather best-mode trajectory: contiguous 128B, 128B-aligned ----
    const float4* traj =
        (const float4*)(preds + (((size_t)b * AA + a) * MM + bm) * (TT * 2));

    float4 v[TT / 2];
#pragma unroll
    for (int q = 0; q < TT / 2; q++) v[q] = __ldg(&traj[q]);   // 8 independent LDG.128

    float xmin[TT], ymin[TT];
#pragma unroll
    for (int q = 0; q < TT / 2; q++) {
        const int t0 = 2 * q;
        {
            float dx = s_ego[t0 * 2 + 0] - v[q].x;
            float dy = s_ego[t0 * 2 + 1] - v[q].y;
            float pen = (dx * dx + dy * dy > DIS_THRESH_SQ) ? 100.0f : conf_pen;
            xmin[t0] = fabsf(dx) + pen;
            ymin[t0] = fabsf(dy) + pen;
        }
        {
            float dx = s_ego[(t0 + 1) * 2 + 0] - v[q].z;
            float dy = s_ego[(t0 + 1) * 2 + 1] - v[q].w;
            float pen = (dx * dx + dy * dy > DIS_THRESH_SQ) ? 100.0f : conf_pen;
            xmin[t0 + 1] = fabsf(dx) + pen;
            ymin[t0 + 1] = fabsf(dy) + pen;
        }
    }

    // ---- intra-warp min reduction (32 agents), all 16 timesteps ----
#pragma unroll
    for (int t = 0; t < TT; t++) {
#pragma unroll
        for (int o = 16; o > 0; o >>= 1) {
            xmin[t] = fminf(xmin[t], __shfl_xor_sync(0xffffffffu, xmin[t], o));
            ymin[t] = fminf(ymin[t], __shfl_xor_sync(0xffffffffu, ymin[t], o));
        }
    }
    if (lane == 0) {
#pragma unroll
        for (int t = 0; t < TT; t++) { s_xw[wid][t] = xmin[t]; s_yw[wid][t] = ymin[t]; }
    }
    __syncthreads();

    // ---- cross-warp min + loss transform + block sum (warp 0) ----
    if (tid < 32) {
        float contrib = 0.0f;
        if (lane < TT) {
            float xm = s_xw[0][lane];
            float ym = s_yw[0][lane];
#pragma unroll
            for (int w = 1; w < NWARPS; w++) {
                xm = fminf(xm, s_xw[w][lane]);
                ym = fminf(ym, s_yw[w][lane]);
            }
            float xl = (xm <= X_DIS_THRESH) ? (X_DIS_THRESH - xm) : 0.0f;
            float yl = (ym <= Y_DIS_THRESH) ? (Y_DIS_THRESH - ym) : 0.0f;
            contrib = (xl + yl) * s_pmask[lane];
        }
#pragma unroll
        for (int o = 16; o > 0; o >>= 1)
            contrib += __shfl_xor_sync(0xffffffffu, contrib, o);
        if (lane == 0)
            atomicAdd(out, contrib * MEAN_SCALE);
    }
}

extern "C" void kernel_launch(void* const* d_in, const int* in_sizes, int n_in,
                              void* d_out, int out_size)
{
    const float* ego_plan = (const float*)d_in[0];  // [B,T,2]
    const float* preds    = (const float*)d_in[1];  // [B,A,M,T,2]
    const float* scores   = (const float*)d_in[2];  // [B,A,M]
    const float* pmask    = (const float*)d_in[3];  // [B,T]
    float* out = (float*)d_out;

    zero_out_kernel<<<1, 1>>>(out);
    plan_pred_collision_loss_kernel<<<BB, THREADS>>>(ego_plan, preds, scores, pmask, out);
}

// round 5
// speedup vs baseline: 1.4060x; 1.4060x over previous
#include <cuda_runtime.h>

// Problem shape (fixed by reference setup_inputs)
#define BB 128
#define AA 1024
#define MM 6
#define TT 16
#define THREADS 1024
#define NWARPS (THREADS / 32)               // 32 warps; each warp owns 32 agents

#define AGENT_THRESH 0.5f
#define X_DIS_THRESH 1.5f
#define Y_DIS_THRESH 3.0f
#define DIS_THRESH_SQ 9.0f                  // dist > 3  <=>  dx*dx+dy*dy > 9
#define MEAN_SCALE (1.0f / (float)(BB * TT * 2))

__global__ void zero_out_kernel(float* out) { out[0] = 0.0f; }

__global__ __launch_bounds__(THREADS, 1)
void plan_pred_collision_loss_kernel(
    const float* __restrict__ ego_plan,   // [B, T, 2]  (T*2 == 32: one elem per lane)
    const float* __restrict__ preds,      // [B, A, M, T, 2]  (one traj == 128B)
    const float* __restrict__ scores,     // [B, A, M]
    const float* __restrict__ pmask,      // [B, T]
    float* __restrict__ out)              // scalar
{
    const int b    = blockIdx.x;
    const int tid  = threadIdx.x;
    const int wid  = tid >> 5;
    const int lane = tid & 31;

    __shared__ float s_scores[NWARPS][MM * 32];   // 24 KB: coalesced score staging
    __shared__ float s_red[NWARPS][32];           // 4 KB: cross-warp min

    // ---- coalesced score load: 192 contiguous floats per warp ----
    const float* sbase = scores + ((size_t)b * AA + (size_t)wid * 32) * MM;
#pragma unroll
    for (int i = 0; i < MM; i++)
        s_scores[wid][i * 32 + lane] = __ldg(&sbase[i * 32 + lane]);
    __syncwarp();

    // ---- per-lane argmax for agent (wid*32 + lane), first-max wins ----
    float best = s_scores[wid][lane * MM];
    int   bm   = 0;
#pragma unroll
    for (int m = 1; m < MM; m++) {
        float v = s_scores[wid][lane * MM + m];
        if (v > best) { best = v; bm = m; }
    }
    const float pen_lane = (best < AGENT_THRESH) ? 100.0f : 0.0f;

    // lane l permanently owns ego element l  (t = l>>1, coord = l&1)
    const float e = __ldg(&ego_plan[b * 32 + lane]);

    // ---- warp-cooperative trajectory gather: 1 coalesced LDG.32 per agent ----
    float acc = 1e30f;
    const size_t warp_agent0 = (size_t)b * AA + (size_t)wid * 32;
#pragma unroll 8
    for (int j = 0; j < 32; j++) {
        const int   bmj  = __shfl_sync(0xffffffffu, bm, j);
        const float penj = __shfl_sync(0xffffffffu, pen_lane, j);
        const float* tp  = preds + ((warp_agent0 + j) * MM + bmj) * (TT * 2);
        const float v = __ldg(&tp[lane]);           // 32 lanes = one 128B line
        const float d = e - v;
        const float dp = __shfl_xor_sync(0xffffffffu, d, 1);  // partner coord
        const float distsq = d * d + dp * dp;
        const float pen = (distsq > DIS_THRESH_SQ) ? 100.0f : penj;
        acc = fminf(acc, fabsf(d) + pen);
    }

    // ---- cross-warp min over the 32 warps (1024 agents total) ----
    s_red[wid][lane] = acc;
    __syncthreads();

    if (tid < 32) {
        float m = s_red[0][lane];
#pragma unroll
        for (int w = 1; w < NWARPS; w++)
            m = fminf(m, s_red[w][lane]);

        const float thr  = (lane & 1) ? Y_DIS_THRESH : X_DIS_THRESH;
        const float loss = (m <= thr) ? (thr - m) : 0.0f;
        const float pm   = __ldg(&pmask[b * TT + (lane >> 1)]);
        float c = loss * pm;
#pragma unroll
        for (int o = 16; o > 0; o >>= 1)
            c += __shfl_xor_sync(0xffffffffu, c, o);
        if (lane == 0)
            atomicAdd(out, c * MEAN_SCALE);
    }
}

extern "C" void kernel_launch(void* const* d_in, const int* in_sizes, int n_in,
                              void* d_out, int out_size)
{
    const float* ego_plan = (const float*)d_in[0];  // [B,T,2]
    const float* preds    = (const float*)d_in[1];  // [B,A,M,T,2]
    const float* scores   = (const float*)d_in[2];  // [B,A,M]
    const float* pmask    = (const float*)d_in[3];  // [B,T]
    float* out = (float*)d_out;

    zero_out_kernel<<<1, 1>>>(out);
    plan_pred_collision_loss_kernel<<<BB, THREADS>>>(ego_plan, preds, scores, pmask, out);
}

// round 10
// speedup vs baseline: 1.7380x; 1.2362x over previous
#include <cuda_runtime.h>
#include <stdint.h>

// Problem shape (fixed by reference setup_inputs)
#define BB 128
#define AA 1024
#define MM 6
#define TT 16
#define THREADS 1024
#define NWARPS (THREADS / 32)               // 32 warps; each warp owns 32 agents

#define AGENT_THRESH 0.5f
#define X_DIS_THRESH 1.5f
#define Y_DIS_THRESH 3.0f
#define DIS_THRESH_SQ 9.0f                  // dist > 3  <=>  dx*dx+dy*dy > 9
#define MEAN_SCALE (1.0f / (float)(BB * TT * 2))

__global__ void zero_out_kernel(float* out) { out[0] = 0.0f; }

__global__ __launch_bounds__(THREADS, 1)
void plan_pred_collision_loss_kernel(
    const float* __restrict__ ego_plan,   // [B, T, 2]
    const float* __restrict__ preds,      // [B, A, M, T, 2] (one traj == 128B)
    const float* __restrict__ scores,     // [B, A, M]
    const float* __restrict__ pmask,      // [B, T]
    float* __restrict__ out)              // scalar
{
    const int b    = blockIdx.x;
    const int tid  = threadIdx.x;
    const int wid  = tid >> 5;
    const int lane = tid & 31;
    const int half = lane >> 4;           // 0: even agents, 1: odd agents
    const int t    = lane & 15;           // timestep owned by this lane

    __shared__ float    s_scores[NWARPS][MM * 32];  // 24 KB coalesced score staging
    __shared__ uint32_t s_off[NWARPS][32];          // 4 KB per-agent gather byte offset
    __shared__ float    s_pen[NWARPS][32];          // 4 KB per-agent confidence penalty
    __shared__ float    s_xr[NWARPS][16];           // 2 KB cross-warp x min
    __shared__ float    s_yr[NWARPS][16];           // 2 KB cross-warp y min

    // ---- coalesced score load: 192 contiguous floats per warp ----
    const float* sbase = scores + ((size_t)b * AA + (size_t)wid * 32) * MM;
#pragma unroll
    for (int i = 0; i < MM; i++)
        s_scores[wid][i * 32 + lane] = __ldg(&sbase[i * 32 + lane]);
    __syncwarp();

    // ---- per-lane argmax for agent (wid*32 + lane), first-max wins ----
    float best = s_scores[wid][lane * MM];
    int   bm   = 0;
#pragma unroll
    for (int m = 1; m < MM; m++) {
        float v = s_scores[wid][lane * MM + m];
        if (v > best) { best = v; bm = m; }
    }
    // byte offset of this agent's best-mode trajectory (fits in u32: max ~100.7MB)
    const uint32_t g = (uint32_t)(b * AA + wid * 32 + lane);
    s_off[wid][lane] = (g * MM + (uint32_t)bm) * (TT * 2 * 4);
    s_pen[wid][lane] = (best < AGENT_THRESH) ? 100.0f : 0.0f;
    __syncwarp();

    // lane owns timestep t of its half's agents: ego (x,y) for t
    const float2 eg = __ldg(&((const float2*)(ego_plan + b * TT * 2))[t]);

    // ---- shuffle-free mainloop: 2 agents/iter, float2 per lane ----
    float xmin = 1e30f, ymin = 1e30f;
#pragma unroll
    for (int j = 0; j < 16; j++) {
        const int a0 = 2 * j + half;                 // agent within warp
        const uint32_t off  = s_off[wid][a0];        // broadcast LDS
        const float    penj = s_pen[wid][a0];
        const float2 v = __ldg((const float2*)((const char*)preds + off + t * 8));
        const float dx = eg.x - v.x;
        const float dy = eg.y - v.y;
        const float pen = (dx * dx + dy * dy > DIS_THRESH_SQ) ? 100.0f : penj;
        xmin = fminf(xmin, fabsf(dx) + pen);
        ymin = fminf(ymin, fabsf(dy) + pen);
    }

    // combine the two halves (even/odd agents) -> per-timestep min over 32 agents
    xmin = fminf(xmin, __shfl_xor_sync(0xffffffffu, xmin, 16));
    ymin = fminf(ymin, __shfl_xor_sync(0xffffffffu, ymin, 16));
    if (lane < 16) { s_xr[wid][lane] = xmin; s_yr[wid][lane] = ymin; }
    __syncthreads();

    // ---- cross-warp min (32 warps = 1024 agents) + loss + block sum ----
    if (tid < 32) {
        const int tt = lane & 15;
        const bool isY = lane >= 16;
        float m = isY ? s_yr[0][tt] : s_xr[0][tt];
#pragma unroll
        for (int w = 1; w < NWARPS; w++)
            m = fminf(m, isY ? s_yr[w][tt] : s_xr[w][tt]);

        const float thr  = isY ? Y_DIS_THRESH : X_DIS_THRESH;
        const float loss = (m <= thr) ? (thr - m) : 0.0f;
        const float pm   = __ldg(&pmask[b * TT + tt]);
        float c = loss * pm;
#pragma unroll
        for (int o = 16; o > 0; o >>= 1)
            c += __shfl_xor_sync(0xffffffffu, c, o);
        if (lane == 0)
            atomicAdd(out, c * MEAN_SCALE);
    }
}

extern "C" void kernel_launch(void* const* d_in, const int* in_sizes, int n_in,
                              void* d_out, int out_size)
{
    const float* ego_plan = (const float*)d_in[0];  // [B,T,2]
    const float* preds    = (const float*)d_in[1];  // [B,A,M,T,2]
    const float* scores   = (const float*)d_in[2];  // [B,A,M]
    const float* pmask    = (const float*)d_in[3];  // [B,T]
    float* out = (float*)d_out;

    zero_out_kernel<<<1, 1>>>(out);
    plan_pred_collision_loss_kernel<<<BB, THREADS>>>(ego_plan, preds, scores, pmask, out);
}